// round 7
// baseline (speedup 1.0000x reference)
#include <cuda_runtime.h>
#include <cuda_bf16.h>

#define B_ 4
#define T_ 2048
#define C_ 1024
#define H_ 16
#define D_ 64
#define M_ (B_*T_)   // 8192

// Scratch for projected q,k,v in [B,T,C] layout (head h = cols h*64..h*64+63)
__device__ float g_q[M_*C_];
__device__ float g_k[M_*C_];
__device__ float g_v[M_*C_];

// Packed dual-FMA: d = a*b + d on two fp32 lanes (B300 FFMA2, only reachable via PTX)
__device__ __forceinline__ void fma2(float2 &d, float2 a, float2 b) {
    asm("fma.rn.f32x2 %0, %1, %2, %0;"
        : "+l"(reinterpret_cast<unsigned long long &>(d))
        : "l"(reinterpret_cast<unsigned long long &>(a)),
          "l"(reinterpret_cast<unsigned long long &>(b)));
}

// ---------------------------------------------------------------------------
// Kernel 1: y = x @ W^T + b for W in {Wq,Wk,Wv}  (blockIdx.z selects)
// Block tile 64(m) x 128(n), BK=16. 256 threads, 4m x 8n per thread (FFMA2).
// ---------------------------------------------------------------------------
__global__ void __launch_bounds__(256) qkv_kernel(
    const float* __restrict__ x,
    const float* __restrict__ Wq, const float* __restrict__ bq,
    const float* __restrict__ Wk, const float* __restrict__ bk,
    const float* __restrict__ Wv, const float* __restrict__ bv)
{
    __shared__ float As[16*68];    // [kk][m], padded
    __shared__ float Bs[16*132];   // [kk][n], padded

    const float* W; const float* bias; float* dst;
    if (blockIdx.z == 0)      { W = Wq; bias = bq; dst = g_q; }
    else if (blockIdx.z == 1) { W = Wk; bias = bk; dst = g_k; }
    else                      { W = Wv; bias = bv; dst = g_v; }

    const int tid = threadIdx.x;
    const int tx  = tid & 15;          // n-dir: 8 cols each
    const int ty  = tid >> 4;          // m-dir: 4 rows each
    const int m0  = blockIdx.y * 64;
    const int n0  = blockIdx.x * 128;

    const int lrow = tid >> 2;         // 0..63
    const int lcol = (tid & 3) * 4;    // 0,4,8,12

    float2 acc[4][4];
    #pragma unroll
    for (int i = 0; i < 4; i++)
        #pragma unroll
        for (int j = 0; j < 4; j++) acc[i][j] = make_float2(0.f, 0.f);

    for (int k0 = 0; k0 < C_; k0 += 16) {
        float4 a  = *(const float4*)&x[(m0 + lrow)*C_ + k0 + lcol];
        float4 b0 = *(const float4*)&W[(n0 + lrow)*C_ + k0 + lcol];
        float4 b1 = *(const float4*)&W[(n0 + 64 + lrow)*C_ + k0 + lcol];
        __syncthreads();   // previous tile fully consumed before overwrite
        As[(lcol+0)*68 + lrow] = a.x;
        As[(lcol+1)*68 + lrow] = a.y;
        As[(lcol+2)*68 + lrow] = a.z;
        As[(lcol+3)*68 + lrow] = a.w;
        Bs[(lcol+0)*132 + lrow] = b0.x;
        Bs[(lcol+1)*132 + lrow] = b0.y;
        Bs[(lcol+2)*132 + lrow] = b0.z;
        Bs[(lcol+3)*132 + lrow] = b0.w;
        Bs[(lcol+0)*132 + 64 + lrow] = b1.x;
        Bs[(lcol+1)*132 + 64 + lrow] = b1.y;
        Bs[(lcol+2)*132 + 64 + lrow] = b1.z;
        Bs[(lcol+3)*132 + 64 + lrow] = b1.w;
        __syncthreads();

        #pragma unroll
        for (int kk = 0; kk < 16; kk++) {
            float4 a4 = *(const float4*)&As[kk*68 + ty*4];
            float4 p0 = *(const float4*)&Bs[kk*132 + tx*8];
            float4 p1 = *(const float4*)&Bs[kk*132 + tx*8 + 4];
            float2 ap[4] = { make_float2(a4.x,a4.x), make_float2(a4.y,a4.y),
                             make_float2(a4.z,a4.z), make_float2(a4.w,a4.w) };
            float2 bp[4] = { make_float2(p0.x,p0.y), make_float2(p0.z,p0.w),
                             make_float2(p1.x,p1.y), make_float2(p1.z,p1.w) };
            #pragma unroll
            for (int mi = 0; mi < 4; mi++)
                #pragma unroll
                for (int nj = 0; nj < 4; nj++)
                    fma2(acc[mi][nj], ap[mi], bp[nj]);
        }
    }

    #pragma unroll
    for (int mi = 0; mi < 4; mi++) {
        int m = m0 + ty*4 + mi;
        #pragma unroll
        for (int nj = 0; nj < 4; nj++) {
            int n = n0 + tx*8 + nj*2;
            float2 v = acc[mi][nj];
            v.x += bias[n];
            v.y += bias[n+1];
            *(float2*)&dst[m*C_ + n] = v;
        }
    }
}

// ---------------------------------------------------------------------------
// Kernel 2: flash attention. One block = (b,h) x 64 q-rows; stream K/V in
// 64-row tiles. 256 threads; S and O tiles are 4x4 per thread (FFMA2 pairs).
// ---------------------------------------------------------------------------
#define TILE_F (64*68)
#define SM_ATTN (4*TILE_F*4)   // 4 tiles * 4352 floats * 4B = 69632 bytes

__global__ void __launch_bounds__(256) attn_kernel(float* __restrict__ out)
{
    extern __shared__ float sm[];
    float* Qs = sm;              // [d][i]  (scaled by 1/8)
    float* Ks = sm + TILE_F;     // [d][j]
    float* Vs = sm + 2*TILE_F;   // [j][d]
    float* Ps = sm + 3*TILE_F;   // [i][j]

    const int tid = threadIdx.x;
    const int tx  = tid & 15;    // j / d dir: 4 each
    const int ty  = tid >> 4;    // i dir: 4 each
    const int bh  = blockIdx.y;
    const int b   = bh >> 4;
    const int h   = bh & 15;
    const int i0  = blockIdx.x * 64;

    const int ld = tid & 63;     // feature lane for loads
    const int lr = tid >> 6;     // 0..3

    // Load Q tile once, transposed to [d][i], fold in softmax scale
    {
        const float* qp = g_q + (b*T_ + i0)*C_ + h*D_ + ld;
        #pragma unroll
        for (int r = 0; r < 16; r++) {
            int i = r*4 + lr;
            Qs[ld*68 + i] = qp[i*C_] * 0.125f;
        }
    }

    float2 o[4][2];
    float mrow[4], lsum[4];
    #pragma unroll
    for (int mi = 0; mi < 4; mi++) {
        o[mi][0] = o[mi][1] = make_float2(0.f, 0.f);
        mrow[mi] = -1e30f;
        lsum[mi] = 0.f;
    }

    for (int j0 = 0; j0 < T_; j0 += 64) {
        const float* kp = g_k + (b*T_ + j0)*C_ + h*D_ + ld;
        const float* vp = g_v + (b*T_ + j0)*C_ + h*D_ + ld;
        __syncthreads();   // previous tile's Ks/Vs/Ps reads complete
        #pragma unroll
        for (int r = 0; r < 16; r++) {
            int j = r*4 + lr;
            Ks[ld*68 + j] = kp[j*C_];
            Vs[j*68 + ld] = vp[j*C_];
        }
        __syncthreads();

        // S = Q K^T (scaled) : 4x4 per thread as FFMA2 pairs
        float2 s[4][2];
        #pragma unroll
        for (int mi = 0; mi < 4; mi++) s[mi][0] = s[mi][1] = make_float2(0.f, 0.f);

        #pragma unroll 16
        for (int d = 0; d < 64; d++) {
            float4 a4 = *(const float4*)&Qs[d*68 + ty*4];
            float4 b4 = *(const float4*)&Ks[d*68 + tx*4];
            float2 bp0 = make_float2(b4.x, b4.y);
            float2 bp1 = make_float2(b4.z, b4.w);
            float2 a0 = make_float2(a4.x, a4.x);
            float2 a1 = make_float2(a4.y, a4.y);
            float2 a2 = make_float2(a4.z, a4.z);
            float2 a3 = make_float2(a4.w, a4.w);
            fma2(s[0][0], a0, bp0); fma2(s[0][1], a0, bp1);
            fma2(s[1][0], a1, bp0); fma2(s[1][1], a1, bp1);
            fma2(s[2][0], a2, bp0); fma2(s[2][1], a2, bp1);
            fma2(s[3][0], a3, bp0); fma2(s[3][1], a3, bp1);
        }

        // Online softmax update (row stats replicated across the 16 tx lanes)
        #pragma unroll
        for (int mi = 0; mi < 4; mi++) {
            float rm = fmaxf(fmaxf(s[mi][0].x, s[mi][0].y),
                             fmaxf(s[mi][1].x, s[mi][1].y));
            #pragma unroll
            for (int sh = 1; sh < 16; sh <<= 1)
                rm = fmaxf(rm, __shfl_xor_sync(0xffffffffu, rm, sh));
            float mn = fmaxf(mrow[mi], rm);
            float p0 = __expf(s[mi][0].x - mn);
            float p1 = __expf(s[mi][0].y - mn);
            float p2 = __expf(s[mi][1].x - mn);
            float p3 = __expf(s[mi][1].y - mn);
            float rs = (p0 + p1) + (p2 + p3);
            #pragma unroll
            for (int sh = 1; sh < 16; sh <<= 1)
                rs += __shfl_xor_sync(0xffffffffu, rs, sh);
            float al = __expf(mrow[mi] - mn);
            lsum[mi] = lsum[mi]*al + rs;
            mrow[mi] = mn;
            o[mi][0].x *= al; o[mi][0].y *= al;
            o[mi][1].x *= al; o[mi][1].y *= al;
            *(float4*)&Ps[(ty*4+mi)*68 + tx*4] = make_float4(p0, p1, p2, p3);
        }
        __syncthreads();

        // O += P V : P read is a warp-broadcast, V read is float4
        #pragma unroll 16
        for (int j = 0; j < 64; j++) {
            float4 v4 = *(const float4*)&Vs[j*68 + tx*4];
            float2 vb0 = make_float2(v4.x, v4.y);
            float2 vb1 = make_float2(v4.z, v4.w);
            #pragma unroll
            for (int mi = 0; mi < 4; mi++) {
                float pf = Ps[(ty*4+mi)*68 + j];
                float2 pp = make_float2(pf, pf);
                fma2(o[mi][0], pp, vb0);
                fma2(o[mi][1], pp, vb1);
            }
        }
    }

    #pragma unroll
    for (int mi = 0; mi < 4; mi++) {
        float inv = 1.0f / lsum[mi];
        float4 r = make_float4(o[mi][0].x*inv, o[mi][0].y*inv,
                               o[mi][1].x*inv, o[mi][1].y*inv);
        int row = i0 + ty*4 + mi;
        *(float4*)&out[(b*T_ + row)*C_ + h*D_ + tx*4] = r;
    }
}

extern "C" void kernel_launch(void* const* d_in, const int* in_sizes, int n_in,
                              void* d_out, int out_size)
{
    const float* qx = (const float*)d_in[0];
    const float* Wq = (const float*)d_in[1];
    const float* bq = (const float*)d_in[2];
    const float* Wk = (const float*)d_in[3];
    const float* bk = (const float*)d_in[4];
    const float* Wv = (const float*)d_in[5];
    const float* bv = (const float*)d_in[6];
    float* out = (float*)d_out;

    qkv_kernel<<<dim3(C_/128, M_/64, 3), 256>>>(qx, Wq, bq, Wk, bk, Wv, bv);

    static bool attr_set_done = false;  // idempotent attribute set (not a stream op)
    cudaFuncSetAttribute(attn_kernel,
                         cudaFuncAttributeMaxDynamicSharedMemorySize, SM_ATTN);
    (void)attr_set_done;

    attn_kernel<<<dim3(T_/64, B_*H_), 256, SM_ATTN>>>(out);
}

// round 14
// speedup vs baseline: 1.5977x; 1.5977x over previous
#include <cuda_runtime.h>
#include <cuda_bf16.h>
#include <cstdint>

#define B_ 4
#define T_ 2048
#define C_ 1024
#define H_ 16
#define D_ 64
#define M_ (B_*T_)   // 8192

__device__ float g_q[M_*C_];
__device__ float g_k[M_*C_];
__device__ float g_v[M_*C_];
__device__ __nv_bfloat16 g_xh[M_*C_];
__device__ __nv_bfloat16 g_xl[M_*C_];
__device__ __nv_bfloat16 g_wh[3*C_*C_];
__device__ __nv_bfloat16 g_wl[3*C_*C_];

// Packed dual-FMA (B300 FFMA2)
__device__ __forceinline__ void fma2(float2 &d, float2 a, float2 b) {
    asm("fma.rn.f32x2 %0, %1, %2, %0;"
        : "+l"(reinterpret_cast<unsigned long long &>(d))
        : "l"(reinterpret_cast<unsigned long long &>(a)),
          "l"(reinterpret_cast<unsigned long long &>(b)));
}

// Warp-level bf16 tensor-core MMA: D(f32) += A(bf16) * B(bf16), m16n8k16
__device__ __forceinline__ void mma16816(float* c, const uint32_t* a, const uint32_t* b) {
    asm volatile("mma.sync.aligned.m16n8k16.row.col.f32.bf16.bf16.f32 "
        "{%0,%1,%2,%3}, {%4,%5,%6,%7}, {%8,%9}, {%0,%1,%2,%3};"
        : "+f"(c[0]), "+f"(c[1]), "+f"(c[2]), "+f"(c[3])
        : "r"(a[0]), "r"(a[1]), "r"(a[2]), "r"(a[3]), "r"(b[0]), "r"(b[1]));
}

// ---------------------------------------------------------------------------
// Kernel 0: fp32 -> bf16 hi + bf16 lo split for x and Wq/Wk/Wv
// ---------------------------------------------------------------------------
#define NX4 (M_*C_/4)
#define NW4 (C_*C_/4)
#define NT4 (NX4 + 3*NW4)

__global__ void __launch_bounds__(256) split_kernel(
    const float* __restrict__ x,  const float* __restrict__ Wq,
    const float* __restrict__ Wk, const float* __restrict__ Wv)
{
    int i4 = blockIdx.x * 256 + threadIdx.x;
    if (i4 >= NT4) return;
    const float* src; __nv_bfloat16 *dh, *dl; size_t off4;
    if (i4 < NX4) { src = x; dh = g_xh; dl = g_xl; off4 = i4; }
    else {
        int j = i4 - NX4;
        int w = j / NW4; off4 = j - w * NW4;
        src = (w == 0) ? Wq : (w == 1) ? Wk : Wv;
        dh = g_wh + (size_t)w * C_ * C_;
        dl = g_wl + (size_t)w * C_ * C_;
    }
    float4 v = ((const float4*)src)[off4];
    __nv_bfloat16 h0 = __float2bfloat16(v.x), h1 = __float2bfloat16(v.y);
    __nv_bfloat16 h2 = __float2bfloat16(v.z), h3 = __float2bfloat16(v.w);
    __nv_bfloat16 l0 = __float2bfloat16(v.x - __bfloat162float(h0));
    __nv_bfloat16 l1 = __float2bfloat16(v.y - __bfloat162float(h1));
    __nv_bfloat16 l2 = __float2bfloat16(v.z - __bfloat162float(h2));
    __nv_bfloat16 l3 = __float2bfloat16(v.w - __bfloat162float(h3));
    __nv_bfloat162* ph = (__nv_bfloat162*)(dh + 4*off4);
    __nv_bfloat162* pl = (__nv_bfloat162*)(dl + 4*off4);
    ph[0] = __nv_bfloat162(h0, h1); ph[1] = __nv_bfloat162(h2, h3);
    pl[0] = __nv_bfloat162(l0, l1); pl[1] = __nv_bfloat162(l2, l3);
}

// ---------------------------------------------------------------------------
// Kernel 1: y = x @ W^T + b via HMMA bf16 split (hh + h*lo + lo*h).
// CTA tile 128(m) x 128(n), BK=32. 8 warps, each 64x32 (4x4 m16n8k16 tiles).
// Row stride 40 bf16 (80B = 20 words): r*20 mod 32 hits each 4-word group
// once across 8 rows -> conflict-free fragment loads.
// ---------------------------------------------------------------------------
#define BK_ 32
#define PADK 40

__global__ void __launch_bounds__(256, 2) qkv_hmma_kernel(
    const float* __restrict__ bq, const float* __restrict__ bk2,
    const float* __restrict__ bv)
{
    __shared__ __nv_bfloat16 Ash[128*PADK];
    __shared__ __nv_bfloat16 Asl[128*PADK];
    __shared__ __nv_bfloat16 Bsh[128*PADK];
    __shared__ __nv_bfloat16 Bsl[128*PADK];
    __shared__ float sbias[128];

    const int tid  = threadIdx.x;
    const int lane = tid & 31;
    const int wid  = tid >> 5;
    const int z    = blockIdx.z;
    const int m0   = blockIdx.y * 128;
    const int n0   = blockIdx.x * 128;

    const float* bias = (z == 0) ? bq : (z == 1) ? bk2 : bv;
    float* dst = (z == 0) ? g_q : (z == 1) ? g_k : g_v;
    const __nv_bfloat16* wh = g_wh + (size_t)z * C_ * C_;
    const __nv_bfloat16* wl = g_wl + (size_t)z * C_ * C_;

    if (tid < 128) sbias[tid] = bias[n0 + tid];

    const int wm = (wid & 1) * 64;     // warp m-offset in CTA tile
    const int wn = (wid >> 1) * 32;    // warp n-offset

    const int lrow = tid >> 1;         // 0..127 (fill row)
    const int lk   = (tid & 1) * 16;   // bf16 k-offset 0 or 16

    float acc[4][4][4];
    #pragma unroll
    for (int mt = 0; mt < 4; mt++)
        #pragma unroll
        for (int nt = 0; nt < 4; nt++)
            acc[mt][nt][0] = acc[mt][nt][1] = acc[mt][nt][2] = acc[mt][nt][3] = 0.f;

    for (int k0 = 0; k0 < C_; k0 += BK_) {
        const uint4* pah = (const uint4*)(g_xh + (size_t)(m0 + lrow) * C_ + k0 + lk);
        const uint4* pal = (const uint4*)(g_xl + (size_t)(m0 + lrow) * C_ + k0 + lk);
        const uint4* pbh = (const uint4*)(wh   + (size_t)(n0 + lrow) * C_ + k0 + lk);
        const uint4* pbl = (const uint4*)(wl   + (size_t)(n0 + lrow) * C_ + k0 + lk);
        uint4 vah0 = pah[0], vah1 = pah[1];
        uint4 val0 = pal[0], val1 = pal[1];
        uint4 vbh0 = pbh[0], vbh1 = pbh[1];
        uint4 vbl0 = pbl[0], vbl1 = pbl[1];

        __syncthreads();   // previous tile fully consumed
        *(uint4*)&Ash[lrow*PADK + lk]     = vah0;
        *(uint4*)&Ash[lrow*PADK + lk + 8] = vah1;
        *(uint4*)&Asl[lrow*PADK + lk]     = val0;
        *(uint4*)&Asl[lrow*PADK + lk + 8] = val1;
        *(uint4*)&Bsh[lrow*PADK + lk]     = vbh0;
        *(uint4*)&Bsh[lrow*PADK + lk + 8] = vbh1;
        *(uint4*)&Bsl[lrow*PADK + lk]     = vbl0;
        *(uint4*)&Bsl[lrow*PADK + lk + 8] = vbl1;
        __syncthreads();

        #pragma unroll
        for (int ks = 0; ks < 2; ks++) {
            const int kc = ks*16 + (lane & 3)*2;   // k column pair base
            const int fr = lane >> 2;              // fragment row 0..7

            uint32_t bh[4][2], bl[4][2];
            #pragma unroll
            for (int nt = 0; nt < 4; nt++) {
                int nr = wn + nt*8 + fr;
                bh[nt][0] = *(const uint32_t*)&Bsh[nr*PADK + kc];
                bh[nt][1] = *(const uint32_t*)&Bsh[nr*PADK + kc + 8];
                bl[nt][0] = *(const uint32_t*)&Bsl[nr*PADK + kc];
                bl[nt][1] = *(const uint32_t*)&Bsl[nr*PADK + kc + 8];
            }
            uint32_t ah[4][4], al[4][4];
            #pragma unroll
            for (int mt = 0; mt < 4; mt++) {
                int mr = wm + mt*16 + fr;
                ah[mt][0] = *(const uint32_t*)&Ash[mr*PADK + kc];
                ah[mt][1] = *(const uint32_t*)&Ash[(mr+8)*PADK + kc];
                ah[mt][2] = *(const uint32_t*)&Ash[mr*PADK + kc + 8];
                ah[mt][3] = *(const uint32_t*)&Ash[(mr+8)*PADK + kc + 8];
                al[mt][0] = *(const uint32_t*)&Asl[mr*PADK + kc];
                al[mt][1] = *(const uint32_t*)&Asl[(mr+8)*PADK + kc];
                al[mt][2] = *(const uint32_t*)&Asl[mr*PADK + kc + 8];
                al[mt][3] = *(const uint32_t*)&Asl[(mr+8)*PADK + kc + 8];
            }
            #pragma unroll
            for (int mt = 0; mt < 4; mt++)
                #pragma unroll
                for (int nt = 0; nt < 4; nt++) {
                    mma16816(acc[mt][nt], ah[mt], bh[nt]);   // hi*hi
                    mma16816(acc[mt][nt], ah[mt], bl[nt]);   // hi*lo
                    mma16816(acc[mt][nt], al[mt], bh[nt]);   // lo*hi
                }
        }
    }

    // Epilogue: c0,c1 = (row, col/col+1); c2,c3 = (row+8, col/col+1)
    #pragma unroll
    for (int mt = 0; mt < 4; mt++) {
        int grow = m0 + wm + mt*16 + (lane >> 2);
        #pragma unroll
        for (int nt = 0; nt < 4; nt++) {
            int lcol = wn + nt*8 + (lane & 3)*2;
            float bx = sbias[lcol], by = sbias[lcol + 1];
            float2 v0 = make_float2(acc[mt][nt][0] + bx, acc[mt][nt][1] + by);
            float2 v1 = make_float2(acc[mt][nt][2] + bx, acc[mt][nt][3] + by);
            *(float2*)&dst[(size_t)grow * C_ + n0 + lcol]       = v0;
            *(float2*)&dst[(size_t)(grow + 8) * C_ + n0 + lcol] = v1;
        }
    }
}

// ---------------------------------------------------------------------------
// Kernel 2: flash attention (fp32 FFMA2). One block = (b,h) x 64 q-rows.
// Conflict-free float4 K-tile stores + float4 P broadcasts in the PV loop.
// ---------------------------------------------------------------------------
#define TILE_F (64*68)
#define SM_ATTN (4*TILE_F*4)   // 69632 bytes

__global__ void __launch_bounds__(256, 3) attn_kernel(float* __restrict__ out)
{
    extern __shared__ float sm[];
    float* Qs = sm;              // [d][i]  (scaled by 1/8)
    float* Ks = sm + TILE_F;     // [d][j]
    float* Vs = sm + 2*TILE_F;   // [j][d]
    float* Ps = sm + 3*TILE_F;   // [i][j]

    const int tid = threadIdx.x;
    const int tx  = tid & 15;
    const int ty  = tid >> 4;
    const int bh  = blockIdx.y;
    const int b   = bh >> 4;
    const int h   = bh & 15;
    const int i0  = blockIdx.x * 64;

    const int ld = tid & 63;
    const int lr = tid >> 6;

    {
        const float* qp = g_q + (size_t)(b*T_ + i0)*C_ + h*D_ + ld;
        #pragma unroll
        for (int r = 0; r < 16; r++) {
            int i = r*4 + lr;
            Qs[ld*68 + i] = qp[(size_t)i*C_] * 0.125f;
        }
    }

    float2 o[4][2];
    float mrow[4], lsum[4];
    #pragma unroll
    for (int mi = 0; mi < 4; mi++) {
        o[mi][0] = o[mi][1] = make_float2(0.f, 0.f);
        mrow[mi] = -1e30f;
        lsum[mi] = 0.f;
    }

    for (int j0 = 0; j0 < T_; j0 += 64) {
        const float* kp = g_k + (size_t)(b*T_ + j0)*C_ + h*D_ + ld;
        const float* vp = g_v + (size_t)(b*T_ + j0)*C_ + h*D_ + ld;
        __syncthreads();
        // K tile: 4 consecutive j per STS.128 -> conflict-free (272B stride)
        #pragma unroll
        for (int q = 0; q < 4; q++) {
            int jb = lr*16 + q*4;
            float4 kv;
            kv.x = kp[(size_t)(jb+0)*C_];
            kv.y = kp[(size_t)(jb+1)*C_];
            kv.z = kp[(size_t)(jb+2)*C_];
            kv.w = kp[(size_t)(jb+3)*C_];
            *(float4*)&Ks[ld*68 + jb] = kv;
        }
        #pragma unroll
        for (int r = 0; r < 16; r++) {
            int j = r*4 + lr;
            Vs[j*68 + ld] = vp[(size_t)j*C_];
        }
        __syncthreads();

        // S = Q K^T (scaled)
        float2 s[4][2];
        #pragma unroll
        for (int mi = 0; mi < 4; mi++) s[mi][0] = s[mi][1] = make_float2(0.f, 0.f);

        #pragma unroll 16
        for (int d = 0; d < 64; d++) {
            float4 a4 = *(const float4*)&Qs[d*68 + ty*4];
            float4 b4 = *(const float4*)&Ks[d*68 + tx*4];
            float2 bp0 = make_float2(b4.x, b4.y);
            float2 bp1 = make_float2(b4.z, b4.w);
            float2 a0 = make_float2(a4.x, a4.x);
            float2 a1 = make_float2(a4.y, a4.y);
            float2 a2 = make_float2(a4.z, a4.z);
            float2 a3 = make_float2(a4.w, a4.w);
            fma2(s[0][0], a0, bp0); fma2(s[0][1], a0, bp1);
            fma2(s[1][0], a1, bp0); fma2(s[1][1], a1, bp1);
            fma2(s[2][0], a2, bp0); fma2(s[2][1], a2, bp1);
            fma2(s[3][0], a3, bp0); fma2(s[3][1], a3, bp1);
        }

        // Online softmax update
        #pragma unroll
        for (int mi = 0; mi < 4; mi++) {
            float rm = fmaxf(fmaxf(s[mi][0].x, s[mi][0].y),
                             fmaxf(s[mi][1].x, s[mi][1].y));
            #pragma unroll
            for (int sh = 1; sh < 16; sh <<= 1)
                rm = fmaxf(rm, __shfl_xor_sync(0xffffffffu, rm, sh));
            float mn = fmaxf(mrow[mi], rm);
            float p0 = __expf(s[mi][0].x - mn);
            float p1 = __expf(s[mi][0].y - mn);
            float p2 = __expf(s[mi][1].x - mn);
            float p3 = __expf(s[mi][1].y - mn);
            float rs = (p0 + p1) + (p2 + p3);
            #pragma unroll
            for (int sh = 1; sh < 16; sh <<= 1)
                rs += __shfl_xor_sync(0xffffffffu, rs, sh);
            float al = __expf(mrow[mi] - mn);
            lsum[mi] = lsum[mi]*al + rs;
            mrow[mi] = mn;
            o[mi][0].x *= al; o[mi][0].y *= al;
            o[mi][1].x *= al; o[mi][1].y *= al;
            *(float4*)&Ps[(ty*4+mi)*68 + tx*4] = make_float4(p0, p1, p2, p3);
        }
        __syncthreads();

        // O += P V : P via float4 broadcast (4 j at a time), V via float4
        #pragma unroll 4
        for (int jq = 0; jq < 16; jq++) {
            float4 pq[4];
            pq[0] = *(const float4*)&Ps[(ty*4+0)*68 + jq*4];
            pq[1] = *(const float4*)&Ps[(ty*4+1)*68 + jq*4];
            pq[2] = *(const float4*)&Ps[(ty*4+2)*68 + jq*4];
            pq[3] = *(const float4*)&Ps[(ty*4+3)*68 + jq*4];
            const float* pf = (const float*)pq;   // pf[mi*4+q]
            #pragma unroll
            for (int q = 0; q < 4; q++) {
                float4 v4 = *(const float4*)&Vs[(jq*4+q)*68 + tx*4];
                float2 vb0 = make_float2(v4.x, v4.y);
                float2 vb1 = make_float2(v4.z, v4.w);
                #pragma unroll
                for (int mi = 0; mi < 4; mi++) {
                    float2 pp = make_float2(pf[mi*4+q], pf[mi*4+q]);
                    fma2(o[mi][0], pp, vb0);
                    fma2(o[mi][1], pp, vb1);
                }
            }
        }
    }

    #pragma unroll
    for (int mi = 0; mi < 4; mi++) {
        float inv = 1.0f / lsum[mi];
        float4 r = make_float4(o[mi][0].x*inv, o[mi][0].y*inv,
                               o[mi][1].x*inv, o[mi][1].y*inv);
        int row = i0 + ty*4 + mi;
        *(float4*)&out[(size_t)(b*T_ + row)*C_ + h*D_ + tx*4] = r;
    }
}

extern "C" void kernel_launch(void* const* d_in, const int* in_sizes, int n_in,
                              void* d_out, int out_size)
{
    const float* qx = (const float*)d_in[0];
    const float* Wq = (const float*)d_in[1];
    const float* bq = (const float*)d_in[2];
    const float* Wk = (const float*)d_in[3];
    const float* bk = (const float*)d_in[4];
    const float* Wv = (const float*)d_in[5];
    const float* bv = (const float*)d_in[6];
    float* out = (float*)d_out;

    cudaFuncSetAttribute(attn_kernel,
                         cudaFuncAttributeMaxDynamicSharedMemorySize, SM_ATTN);

    split_kernel<<<(NT4 + 255)/256, 256>>>(qx, Wq, Wk, Wv);
    qkv_hmma_kernel<<<dim3(C_/128, M_/128, 3), 256>>>(bq, bk, bv);
    attn_kernel<<<dim3(T_/64, B_*H_), 256, SM_ATTN>>>(out);
}

// round 15
// speedup vs baseline: 2.7298x; 1.7085x over previous
#include <cuda_runtime.h>
#include <cuda_bf16.h>
#include <cstdint>

#define B_ 4
#define T_ 2048
#define C_ 1024
#define H_ 16
#define D_ 64
#define M_ (B_*T_)   // 8192

// bf16 hi/lo splits: inputs (x, W) and projected q/k/v
__device__ __nv_bfloat16 g_xh[M_*C_];
__device__ __nv_bfloat16 g_xl[M_*C_];
__device__ __nv_bfloat16 g_wh[3*C_*C_];
__device__ __nv_bfloat16 g_wl[3*C_*C_];
__device__ __nv_bfloat16 g_qh[M_*C_], g_ql[M_*C_];   // q pre-scaled by 1/8
__device__ __nv_bfloat16 g_kh[M_*C_], g_kl[M_*C_];
__device__ __nv_bfloat16 g_vh[M_*C_], g_vl[M_*C_];

// ---------------------------------------------------------------- helpers
// Warp-level bf16 tensor-core MMA: D(f32) += A(bf16) * B(bf16), m16n8k16
__device__ __forceinline__ void mma16816(float* c, const uint32_t* a, const uint32_t* b) {
    asm volatile("mma.sync.aligned.m16n8k16.row.col.f32.bf16.bf16.f32 "
        "{%0,%1,%2,%3}, {%4,%5,%6,%7}, {%8,%9}, {%0,%1,%2,%3};"
        : "+f"(c[0]), "+f"(c[1]), "+f"(c[2]), "+f"(c[3])
        : "r"(a[0]), "r"(a[1]), "r"(a[2]), "r"(a[3]), "r"(b[0]), "r"(b[1]));
}
__device__ __forceinline__ void ldsm4(uint32_t* r, uint32_t a) {
    asm volatile("ldmatrix.sync.aligned.m8n8.x4.shared.b16 {%0,%1,%2,%3}, [%4];"
        : "=r"(r[0]), "=r"(r[1]), "=r"(r[2]), "=r"(r[3]) : "r"(a));
}
__device__ __forceinline__ void ldsm4t(uint32_t* r, uint32_t a) {
    asm volatile("ldmatrix.sync.aligned.m8n8.x4.trans.shared.b16 {%0,%1,%2,%3}, [%4];"
        : "=r"(r[0]), "=r"(r[1]), "=r"(r[2]), "=r"(r[3]) : "r"(a));
}
__device__ __forceinline__ uint32_t smem_u32(const void* p) {
    uint32_t a;
    asm("{ .reg .u64 t; cvta.to.shared.u64 t, %1; cvt.u32.u64 %0, t; }"
        : "=r"(a) : "l"(p));
    return a;
}
// pack two fp32 into bf16x2: low half = lo, high half = hi
__device__ __forceinline__ uint32_t pack_bf16(float lo, float hi) {
    uint32_t d;
    asm("cvt.rn.bf16x2.f32 %0, %1, %2;" : "=r"(d) : "f"(hi), "f"(lo));
    return d;
}
__device__ __forceinline__ float lo_f(uint32_t u) { return __uint_as_float(u << 16); }
__device__ __forceinline__ float hi_f(uint32_t u) { return __uint_as_float(u & 0xffff0000u); }

// ---------------------------------------------------------------------------
// Kernel 0: fp32 -> bf16 hi + bf16 lo split for x and Wq/Wk/Wv
// ---------------------------------------------------------------------------
#define NX4 (M_*C_/4)
#define NW4 (C_*C_/4)
#define NT4 (NX4 + 3*NW4)

__global__ void __launch_bounds__(256) split_kernel(
    const float* __restrict__ x,  const float* __restrict__ Wq,
    const float* __restrict__ Wk, const float* __restrict__ Wv)
{
    int i4 = blockIdx.x * 256 + threadIdx.x;
    if (i4 >= NT4) return;
    const float* src; __nv_bfloat16 *dh, *dl; size_t off4;
    if (i4 < NX4) { src = x; dh = g_xh; dl = g_xl; off4 = i4; }
    else {
        int j = i4 - NX4;
        int w = j / NW4; off4 = j - w * NW4;
        src = (w == 0) ? Wq : (w == 1) ? Wk : Wv;
        dh = g_wh + (size_t)w * C_ * C_;
        dl = g_wl + (size_t)w * C_ * C_;
    }
    float4 v = ((const float4*)src)[off4];
    uint32_t h01 = pack_bf16(v.x, v.y);
    uint32_t h23 = pack_bf16(v.z, v.w);
    uint32_t l01 = pack_bf16(v.x - lo_f(h01), v.y - hi_f(h01));
    uint32_t l23 = pack_bf16(v.z - lo_f(h23), v.w - hi_f(h23));
    uint32_t* ph = (uint32_t*)(dh + 4*off4);
    uint32_t* pl = (uint32_t*)(dl + 4*off4);
    ph[0] = h01; ph[1] = h23;
    pl[0] = l01; pl[1] = l23;
}

// ---------------------------------------------------------------------------
// Kernel 1: y = x @ W^T + b via HMMA bf16 split (hh + h*lo + lo*h).
// CTA tile 128x128, BK=32. Epilogue writes bf16 hi/lo q/k/v (q scaled 1/8).
// ---------------------------------------------------------------------------
#define BK_ 32
#define PADK 40

__global__ void __launch_bounds__(256, 2) qkv_hmma_kernel(
    const float* __restrict__ bq, const float* __restrict__ bk2,
    const float* __restrict__ bv)
{
    __shared__ __nv_bfloat16 Ash[128*PADK];
    __shared__ __nv_bfloat16 Asl[128*PADK];
    __shared__ __nv_bfloat16 Bsh[128*PADK];
    __shared__ __nv_bfloat16 Bsl[128*PADK];
    __shared__ float sbias[128];

    const int tid  = threadIdx.x;
    const int lane = tid & 31;
    const int wid  = tid >> 5;
    const int z    = blockIdx.z;
    const int m0   = blockIdx.y * 128;
    const int n0   = blockIdx.x * 128;

    const float* bias = (z == 0) ? bq : (z == 1) ? bk2 : bv;
    __nv_bfloat16* dh = (z == 0) ? g_qh : (z == 1) ? g_kh : g_vh;
    __nv_bfloat16* dl = (z == 0) ? g_ql : (z == 1) ? g_kl : g_vl;
    const __nv_bfloat16* wh = g_wh + (size_t)z * C_ * C_;
    const __nv_bfloat16* wl = g_wl + (size_t)z * C_ * C_;

    if (tid < 128) sbias[tid] = bias[n0 + tid];

    const int wm = (wid & 1) * 64;
    const int wn = (wid >> 1) * 32;
    const int lrow = tid >> 1;
    const int lk   = (tid & 1) * 16;

    float acc[4][4][4];
    #pragma unroll
    for (int mt = 0; mt < 4; mt++)
        #pragma unroll
        for (int nt = 0; nt < 4; nt++)
            acc[mt][nt][0] = acc[mt][nt][1] = acc[mt][nt][2] = acc[mt][nt][3] = 0.f;

    for (int k0 = 0; k0 < C_; k0 += BK_) {
        const uint4* pah = (const uint4*)(g_xh + (size_t)(m0 + lrow) * C_ + k0 + lk);
        const uint4* pal = (const uint4*)(g_xl + (size_t)(m0 + lrow) * C_ + k0 + lk);
        const uint4* pbh = (const uint4*)(wh   + (size_t)(n0 + lrow) * C_ + k0 + lk);
        const uint4* pbl = (const uint4*)(wl   + (size_t)(n0 + lrow) * C_ + k0 + lk);
        uint4 vah0 = pah[0], vah1 = pah[1];
        uint4 val0 = pal[0], val1 = pal[1];
        uint4 vbh0 = pbh[0], vbh1 = pbh[1];
        uint4 vbl0 = pbl[0], vbl1 = pbl[1];

        __syncthreads();
        *(uint4*)&Ash[lrow*PADK + lk]     = vah0;
        *(uint4*)&Ash[lrow*PADK + lk + 8] = vah1;
        *(uint4*)&Asl[lrow*PADK + lk]     = val0;
        *(uint4*)&Asl[lrow*PADK + lk + 8] = val1;
        *(uint4*)&Bsh[lrow*PADK + lk]     = vbh0;
        *(uint4*)&Bsh[lrow*PADK + lk + 8] = vbh1;
        *(uint4*)&Bsl[lrow*PADK + lk]     = vbl0;
        *(uint4*)&Bsl[lrow*PADK + lk + 8] = vbl1;
        __syncthreads();

        #pragma unroll
        for (int ks = 0; ks < 2; ks++) {
            const int kc = ks*16 + (lane & 3)*2;
            const int fr = lane >> 2;

            uint32_t bh[4][2], bl[4][2];
            #pragma unroll
            for (int nt = 0; nt < 4; nt++) {
                int nr = wn + nt*8 + fr;
                bh[nt][0] = *(const uint32_t*)&Bsh[nr*PADK + kc];
                bh[nt][1] = *(const uint32_t*)&Bsh[nr*PADK + kc + 8];
                bl[nt][0] = *(const uint32_t*)&Bsl[nr*PADK + kc];
                bl[nt][1] = *(const uint32_t*)&Bsl[nr*PADK + kc + 8];
            }
            uint32_t ah[4][4], al[4][4];
            #pragma unroll
            for (int mt = 0; mt < 4; mt++) {
                int mr = wm + mt*16 + fr;
                ah[mt][0] = *(const uint32_t*)&Ash[mr*PADK + kc];
                ah[mt][1] = *(const uint32_t*)&Ash[(mr+8)*PADK + kc];
                ah[mt][2] = *(const uint32_t*)&Ash[mr*PADK + kc + 8];
                ah[mt][3] = *(const uint32_t*)&Ash[(mr+8)*PADK + kc + 8];
                al[mt][0] = *(const uint32_t*)&Asl[mr*PADK + kc];
                al[mt][1] = *(const uint32_t*)&Asl[(mr+8)*PADK + kc];
                al[mt][2] = *(const uint32_t*)&Asl[mr*PADK + kc + 8];
                al[mt][3] = *(const uint32_t*)&Asl[(mr+8)*PADK + kc + 8];
            }
            #pragma unroll
            for (int mt = 0; mt < 4; mt++)
                #pragma unroll
                for (int nt = 0; nt < 4; nt++) {
                    mma16816(acc[mt][nt], ah[mt], bh[nt]);
                    mma16816(acc[mt][nt], ah[mt], bl[nt]);
                    mma16816(acc[mt][nt], al[mt], bh[nt]);
                }
        }
    }

    // Epilogue: add bias, (scale for q), split to bf16 hi/lo, store
    const float scale = (z == 0) ? 0.125f : 1.0f;
    #pragma unroll
    for (int mt = 0; mt < 4; mt++) {
        int grow = m0 + wm + mt*16 + (lane >> 2);
        #pragma unroll
        for (int nt = 0; nt < 4; nt++) {
            int lcol = wn + nt*8 + (lane & 3)*2;
            float bx = sbias[lcol], by = sbias[lcol + 1];
            float y00 = (acc[mt][nt][0] + bx) * scale;
            float y01 = (acc[mt][nt][1] + by) * scale;
            float y10 = (acc[mt][nt][2] + bx) * scale;
            float y11 = (acc[mt][nt][3] + by) * scale;
            size_t o0 = (size_t)grow * C_ + n0 + lcol;
            size_t o1 = (size_t)(grow + 8) * C_ + n0 + lcol;
            uint32_t h0 = pack_bf16(y00, y01);
            uint32_t l0r = pack_bf16(y00 - lo_f(h0), y01 - hi_f(h0));
            uint32_t h1 = pack_bf16(y10, y11);
            uint32_t l1r = pack_bf16(y10 - lo_f(h1), y11 - hi_f(h1));
            *(uint32_t*)&dh[o0] = h0;  *(uint32_t*)&dl[o0] = l0r;
            *(uint32_t*)&dh[o1] = h1;  *(uint32_t*)&dl[o1] = l1r;
        }
    }
}

// ---------------------------------------------------------------------------
// Kernel 2: HMMA flash attention. CTA = (b,h) x 128 q-rows, 8 warps x 16 rows.
// S and PV on tensor cores with hi/lo splits; P stays in registers (the S
// C-fragment layout == the PV A-fragment layout). ldmatrix everywhere.
// ---------------------------------------------------------------------------
#define PAD 72
#define SM_ATTN ((128*PAD*2 + 64*PAD*4) * 2)   // 73728 bytes

__global__ void __launch_bounds__(256) attn_kernel(float* __restrict__ out)
{
    extern __shared__ __nv_bfloat16 smb[];
    __nv_bfloat16* Qh = smb;                 // [128][PAD]
    __nv_bfloat16* Ql = Qh + 128*PAD;
    __nv_bfloat16* Kh = Ql + 128*PAD;        // [64][PAD]
    __nv_bfloat16* Kl = Kh + 64*PAD;
    __nv_bfloat16* Vh = Kl + 64*PAD;         // [64][PAD]
    __nv_bfloat16* Vl = Vh + 64*PAD;

    const int tid  = threadIdx.x;
    const int lane = tid & 31;
    const int w    = tid >> 5;
    const int bh   = blockIdx.y;
    const int b    = bh >> 4, h = bh & 15;
    const int i0   = blockIdx.x * 128;

    // ---- Q tile fill (once) ----
    {
        int r = tid >> 1;
        int half = (tid & 1) * 32;
        const uint4* sh = (const uint4*)(g_qh + (size_t)(b*T_ + i0 + r)*C_ + h*D_ + half);
        const uint4* sl = (const uint4*)(g_ql + (size_t)(b*T_ + i0 + r)*C_ + h*D_ + half);
        uint4* dhp = (uint4*)&Qh[r*PAD + half];
        uint4* dlp = (uint4*)&Ql[r*PAD + half];
        #pragma unroll
        for (int g = 0; g < 4; g++) { dhp[g] = sh[g]; dlp[g] = sl[g]; }
    }

    const uint32_t sQh = smem_u32(Qh), sQl = smem_u32(Ql);
    const uint32_t sKh = smem_u32(Kh), sKl = smem_u32(Kl);
    const uint32_t sVh = smem_u32(Vh), sVl = smem_u32(Vl);

    // ldmatrix lane offsets (bytes)
    const uint32_t qoff = (uint32_t)(((16*w + (lane & 15))*PAD + (lane >> 4)*8) * 2);
    const uint32_t koff = (uint32_t)((((lane & 7) + ((lane >> 4) & 1)*8)*PAD
                                      + ((lane >> 3) & 1)*8) * 2);
    const uint32_t voff = (uint32_t)((((lane & 7) + ((lane >> 3) & 1)*8)*PAD
                                      + (lane >> 4)*8) * 2);

    float oacc[8][4];
    #pragma unroll
    for (int i = 0; i < 8; i++)
        oacc[i][0] = oacc[i][1] = oacc[i][2] = oacc[i][3] = 0.f;
    float m0 = -1e30f, m1 = -1e30f, l0 = 0.f, l1 = 0.f;

    // K/V tile fill assignment: one warp-pair per array, one row per thread
    const int kvarr = tid >> 6;
    const int kvrow = tid & 63;
    const __nv_bfloat16* gsrc = (kvarr==0) ? g_kh : (kvarr==1) ? g_kl
                               : (kvarr==2) ? g_vh : g_vl;
    __nv_bfloat16* sdst = (kvarr==0) ? Kh : (kvarr==1) ? Kl
                         : (kvarr==2) ? Vh : Vl;
    const size_t gbase = (size_t)(b*T_)*C_ + h*D_;

    for (int jt = 0; jt < 32; jt++) {
        __syncthreads();
        {
            const uint4* s4 = (const uint4*)(gsrc + gbase + (size_t)(jt*64 + kvrow)*C_);
            uint4* d4 = (uint4*)&sdst[kvrow*PAD];
            #pragma unroll
            for (int g = 0; g < 8; g++) d4[g] = s4[g];
        }
        __syncthreads();

        // ---- S = Q K^T (hi/lo split, fp32 accum) ----
        float sacc[8][4];
        #pragma unroll
        for (int i = 0; i < 8; i++)
            sacc[i][0] = sacc[i][1] = sacc[i][2] = sacc[i][3] = 0.f;

        #pragma unroll
        for (int kc = 0; kc < 4; kc++) {
            uint32_t aqh[4], aql[4];
            ldsm4(aqh, sQh + qoff + kc*32);
            ldsm4(aql, sQl + qoff + kc*32);
            #pragma unroll
            for (int ntp = 0; ntp < 4; ntp++) {
                uint32_t bkh[4], bkl[4];
                uint32_t ko = koff + (uint32_t)(ntp*(16*PAD*2) + kc*32);
                ldsm4(bkh, sKh + ko);
                ldsm4(bkl, sKl + ko);
                mma16816(sacc[2*ntp],   aqh, bkh);
                mma16816(sacc[2*ntp],   aqh, bkl);
                mma16816(sacc[2*ntp],   aql, bkh);
                mma16816(sacc[2*ntp+1], aqh, bkh+2);
                mma16816(sacc[2*ntp+1], aqh, bkl+2);
                mma16816(sacc[2*ntp+1], aql, bkh+2);
            }
        }

        // ---- online softmax (rows r, r+8 per thread; quad shfl reduce) ----
        float rm0 = -1e30f, rm1 = -1e30f;
        #pragma unroll
        for (int nt = 0; nt < 8; nt++) {
            rm0 = fmaxf(rm0, fmaxf(sacc[nt][0], sacc[nt][1]));
            rm1 = fmaxf(rm1, fmaxf(sacc[nt][2], sacc[nt][3]));
        }
        rm0 = fmaxf(rm0, __shfl_xor_sync(0xffffffffu, rm0, 1));
        rm0 = fmaxf(rm0, __shfl_xor_sync(0xffffffffu, rm0, 2));
        rm1 = fmaxf(rm1, __shfl_xor_sync(0xffffffffu, rm1, 1));
        rm1 = fmaxf(rm1, __shfl_xor_sync(0xffffffffu, rm1, 2));
        float mn0 = fmaxf(m0, rm0), mn1 = fmaxf(m1, rm1);
        float al0 = __expf(m0 - mn0), al1 = __expf(m1 - mn1);
        m0 = mn0; m1 = mn1;
        float rs0 = 0.f, rs1 = 0.f;
        #pragma unroll
        for (int nt = 0; nt < 8; nt++) {
            sacc[nt][0] = __expf(sacc[nt][0] - mn0);
            sacc[nt][1] = __expf(sacc[nt][1] - mn0);
            sacc[nt][2] = __expf(sacc[nt][2] - mn1);
            sacc[nt][3] = __expf(sacc[nt][3] - mn1);
            rs0 += sacc[nt][0] + sacc[nt][1];
            rs1 += sacc[nt][2] + sacc[nt][3];
        }
        rs0 += __shfl_xor_sync(0xffffffffu, rs0, 1);
        rs0 += __shfl_xor_sync(0xffffffffu, rs0, 2);
        rs1 += __shfl_xor_sync(0xffffffffu, rs1, 1);
        rs1 += __shfl_xor_sync(0xffffffffu, rs1, 2);
        l0 = l0*al0 + rs0;
        l1 = l1*al1 + rs1;
        #pragma unroll
        for (int nt = 0; nt < 8; nt++) {
            oacc[nt][0] *= al0; oacc[nt][1] *= al0;
            oacc[nt][2] *= al1; oacc[nt][3] *= al1;
        }

        // ---- O += P V (P hi/lo built in registers from S fragments) ----
        #pragma unroll
        for (int kc = 0; kc < 4; kc++) {
            uint32_t aph[4], apl[4];
            {
                float x0 = sacc[2*kc][0],   x1 = sacc[2*kc][1];
                float x2 = sacc[2*kc][2],   x3 = sacc[2*kc][3];
                float y0 = sacc[2*kc+1][0], y1 = sacc[2*kc+1][1];
                float y2 = sacc[2*kc+1][2], y3 = sacc[2*kc+1][3];
                aph[0] = pack_bf16(x0, x1);
                aph[1] = pack_bf16(x2, x3);
                aph[2] = pack_bf16(y0, y1);
                aph[3] = pack_bf16(y2, y3);
                apl[0] = pack_bf16(x0 - lo_f(aph[0]), x1 - hi_f(aph[0]));
                apl[1] = pack_bf16(x2 - lo_f(aph[1]), x3 - hi_f(aph[1]));
                apl[2] = pack_bf16(y0 - lo_f(aph[2]), y1 - hi_f(aph[2]));
                apl[3] = pack_bf16(y2 - lo_f(aph[3]), y3 - hi_f(aph[3]));
            }
            #pragma unroll
            for (int ntp = 0; ntp < 4; ntp++) {
                uint32_t bvh[4], bvl[4];
                uint32_t vo = voff + (uint32_t)(kc*(16*PAD*2) + ntp*32);
                ldsm4t(bvh, sVh + vo);
                ldsm4t(bvl, sVl + vo);
                mma16816(oacc[2*ntp],   aph, bvh);
                mma16816(oacc[2*ntp],   aph, bvl);
                mma16816(oacc[2*ntp],   apl, bvh);
                mma16816(oacc[2*ntp+1], aph, bvh+2);
                mma16816(oacc[2*ntp+1], aph, bvl+2);
                mma16816(oacc[2*ntp+1], apl, bvh+2);
            }
        }
    }

    // ---- epilogue ----
    float inv0 = 1.0f / l0, inv1 = 1.0f / l1;
    int r = 16*w + (lane >> 2);
    float* o0 = out + (size_t)(b*T_ + i0 + r)*C_ + h*D_ + (lane & 3)*2;
    float* o1 = o0 + 8*C_;
    #pragma unroll
    for (int nt = 0; nt < 8; nt++) {
        *(float2*)(o0 + nt*8) = make_float2(oacc[nt][0]*inv0, oacc[nt][1]*inv0);
        *(float2*)(o1 + nt*8) = make_float2(oacc[nt][2]*inv1, oacc[nt][3]*inv1);
    }
}

extern "C" void kernel_launch(void* const* d_in, const int* in_sizes, int n_in,
                              void* d_out, int out_size)
{
    const float* qx = (const float*)d_in[0];
    const float* Wq = (const float*)d_in[1];
    const float* bq = (const float*)d_in[2];
    const float* Wk = (const float*)d_in[3];
    const float* bk = (const float*)d_in[4];
    const float* Wv = (const float*)d_in[5];
    const float* bv = (const float*)d_in[6];
    float* out = (float*)d_out;

    cudaFuncSetAttribute(attn_kernel,
                         cudaFuncAttributeMaxDynamicSharedMemorySize, SM_ATTN);

    split_kernel<<<(NT4 + 255)/256, 256>>>(qx, Wq, Wk, Wv);
    qkv_hmma_kernel<<<dim3(C_/128, M_/128, 3), 256>>>(bq, bk, bv);
    attn_kernel<<<dim3(T_/128, B_*H_), 256, SM_ATTN>>>(out);
}